// round 1
// baseline (speedup 1.0000x reference)
#include <cuda_runtime.h>
#include <cuda_bf16.h>

#define H   128
#define BATCH 8
#define TQ  512
#define TK  512

// Device scratch (allocation-free rule: __device__ globals)
__device__ __align__(16) float g_qp[BATCH * TQ * H];
__device__ __align__(16) float g_kp[BATCH * TK * H];

__device__ __forceinline__ float tanha(float x) {
    float y;
    asm("tanh.approx.f32 %0, %1;" : "=f"(y) : "f"(x));
    return y;
}

// ---------------------------------------------------------------------------
// Kernel 1: projections  qp = queries @ Wa_w^T + Wa_b ; kp = keys @ Ua_w^T + Ua_b
// grid = (T/16, B, 2), block = 128 (one thread per output column h)
// ---------------------------------------------------------------------------
__global__ void __launch_bounds__(128) proj_kernel(
    const float* __restrict__ queries, const float* __restrict__ keys,
    const float* __restrict__ Wa_w, const float* __restrict__ Wa_b,
    const float* __restrict__ Ua_w, const float* __restrict__ Ua_b)
{
    const int tile = blockIdx.x;   // 32 tiles of 16 rows
    const int b    = blockIdx.y;
    const int proj = blockIdx.z;

    const float* x    = proj == 0 ? queries : keys;
    const float* W    = proj == 0 ? Wa_w    : Ua_w;
    const float* bias = proj == 0 ? Wa_b    : Ua_b;
    float*       out  = proj == 0 ? g_qp    : g_kp;

    const int t0 = tile * 16;
    __shared__ __align__(16) float xs[16][H];

    const float4* xsrc = (const float4*)(x + (size_t)(b * 512 + t0) * H);
    #pragma unroll
    for (int i = threadIdx.x; i < 16 * H / 4; i += 128)
        ((float4*)xs)[i] = xsrc[i];
    __syncthreads();

    const int h = threadIdx.x;
    float acc[16];
    const float bv = bias[h];
    #pragma unroll
    for (int t = 0; t < 16; t++) acc[t] = bv;

    const float4* Wrow = (const float4*)(W + h * H);
    #pragma unroll 4
    for (int i = 0; i < H / 4; i++) {
        float4 w4 = Wrow[i];
        #pragma unroll
        for (int t = 0; t < 16; t++) {
            float4 xv = ((const float4*)xs[t])[i];
            acc[t] = fmaf(xv.x, w4.x, fmaf(xv.y, w4.y, fmaf(xv.z, w4.z, fmaf(xv.w, w4.w, acc[t]))));
        }
    }

    #pragma unroll
    for (int t = 0; t < 16; t++)
        out[(size_t)(b * 512 + t0 + t) * H + h] = acc[t];
}

// ---------------------------------------------------------------------------
// Kernel 2: scores (tanh additive attention) + softmax + context
// grid = (TQ/8, B), block = 256 (8 warps, one query per warp)
// smem: 64x128 float tile (kp, then reused for keys) + 8x512 scores = 48 KB
// ---------------------------------------------------------------------------
__global__ void __launch_bounds__(256) attn_kernel(
    const float* __restrict__ keys,
    const float* __restrict__ Va_w,
    float* __restrict__ ctx_out,   // (B, TQ, H)
    float* __restrict__ w_out)     // (B, TQ, TK)
{
    extern __shared__ __align__(16) float smem[];
    float* tile = smem;            // 64 * 128 floats (32 KB)
    float* sc   = smem + 64 * H;   // 8 * 512 floats (16 KB)

    const int b    = blockIdx.y;
    const int wid  = threadIdx.x >> 5;
    const int lane = threadIdx.x & 31;
    const int q    = blockIdx.x * 8 + wid;

    const float4 va = ((const float4*)Va_w)[lane];
    const float4 qv = ((const float4*)(g_qp + (size_t)(b * TQ + q) * H))[lane];

    // ---- Phase A: scores[q][k] = sum_h Va[h] * tanh(qp[h] + kp[h]) ----
    for (int kt = 0; kt < TK; kt += 64) {
        __syncthreads();
        const float4* src = (const float4*)(g_kp + (size_t)(b * TK + kt) * H);
        #pragma unroll
        for (int r = 0; r < 8; r++)
            ((float4*)tile)[threadIdx.x + 256 * r] = src[threadIdx.x + 256 * r];
        __syncthreads();

        for (int kk = 0; kk < 64; kk++) {
            float4 kv = ((const float4*)(tile + kk * H))[lane];
            float p;
            p  = va.x * tanha(qv.x + kv.x);
            p += va.y * tanha(qv.y + kv.y);
            p += va.z * tanha(qv.z + kv.z);
            p += va.w * tanha(qv.w + kv.w);
            #pragma unroll
            for (int o = 16; o > 0; o >>= 1)
                p += __shfl_xor_sync(0xffffffffu, p, o);
            if (lane == 0) sc[wid * TK + kt + kk] = p;
        }
    }

    // ---- Phase B: softmax over k (per warp, own row only) ----
    __syncwarp();
    float* myrow = sc + wid * TK;

    float m = -1e30f;
    #pragma unroll
    for (int j = 0; j < 16; j++) m = fmaxf(m, myrow[j * 32 + lane]);
    #pragma unroll
    for (int o = 16; o > 0; o >>= 1)
        m = fmaxf(m, __shfl_xor_sync(0xffffffffu, m, o));

    float ev[16];
    float sum = 0.f;
    #pragma unroll
    for (int j = 0; j < 16; j++) {
        ev[j] = __expf(myrow[j * 32 + lane] - m);
        sum += ev[j];
    }
    #pragma unroll
    for (int o = 16; o > 0; o >>= 1)
        sum += __shfl_xor_sync(0xffffffffu, sum, o);

    const float inv = __fdividef(1.f, sum);
    float* wrow = w_out + (size_t)(b * TQ + q) * TK;
    #pragma unroll
    for (int j = 0; j < 16; j++) {
        float w = ev[j] * inv;
        myrow[j * 32 + lane] = w;
        wrow[j * 32 + lane]  = w;
    }

    // ---- Phase C: context[q][h] = sum_k w[k] * keys[k][h] ----
    float4 acc = make_float4(0.f, 0.f, 0.f, 0.f);
    for (int kt = 0; kt < TK; kt += 64) {
        __syncthreads();   // all warps done reading tile (A) / done with B
        const float4* src = (const float4*)(keys + (size_t)(b * TK + kt) * H);
        #pragma unroll
        for (int r = 0; r < 8; r++)
            ((float4*)tile)[threadIdx.x + 256 * r] = src[threadIdx.x + 256 * r];
        __syncthreads();

        #pragma unroll 4
        for (int kk = 0; kk < 64; kk++) {
            float  w  = myrow[kt + kk];
            float4 kv = ((const float4*)(tile + kk * H))[lane];
            acc.x = fmaf(w, kv.x, acc.x);
            acc.y = fmaf(w, kv.y, acc.y);
            acc.z = fmaf(w, kv.z, acc.z);
            acc.w = fmaf(w, kv.w, acc.w);
        }
    }
    ((float4*)(ctx_out + (size_t)(b * TQ + q) * H))[lane] = acc;
}

// ---------------------------------------------------------------------------
extern "C" void kernel_launch(void* const* d_in, const int* in_sizes, int n_in,
                              void* d_out, int out_size)
{
    const float* queries = (const float*)d_in[0];
    const float* keys    = (const float*)d_in[1];
    const float* Wa_w    = (const float*)d_in[2];
    const float* Wa_b    = (const float*)d_in[3];
    const float* Ua_w    = (const float*)d_in[4];
    const float* Ua_b    = (const float*)d_in[5];
    const float* Va_w    = (const float*)d_in[6];
    // Va_w bias (d_in[7]) cancels in softmax -> unused.

    float* ctx_out = (float*)d_out;                     // (B, TQ, H)
    float* w_out   = ctx_out + BATCH * TQ * H;          // (B, TQ, TK)

    dim3 g1(512 / 16, BATCH, 2);
    proj_kernel<<<g1, 128>>>(queries, keys, Wa_w, Wa_b, Ua_w, Ua_b);

    dim3 g2(TQ / 8, BATCH);
    size_t smem = (64 * H + 8 * TK) * sizeof(float);    // 49152 bytes
    attn_kernel<<<g2, 256, smem>>>(keys, Va_w, ctx_out, w_out);
}